// round 7
// baseline (speedup 1.0000x reference)
#include <cuda_runtime.h>
#include <cuda_fp16.h>

// Problem constants: B=4, C=CO=64, N=16384, K=16
#define NPTS   16384
#define NODES  (4 * NPTS)          // 65536
#define NCH    64

// Scratch (device globals; no allocation allowed)
__device__ __align__(16) float   g_u[NODES * NCH];      // u[node][o]  fp32
__device__ __align__(16) __half2 g_vh[NODES * 32];      // v[node][o]  fp16, 2ch/half2
__device__ __align__(16) __half2 g_hmax[NODES * 32];    // max_k h  fp16
__device__ __align__(16) __half2 g_hmin[NODES * 32];    // min_k h  fp16
__device__ float g_s1[NCH];                             // sum h   per channel
__device__ float g_s2[NCH];                             // sum h^2 per channel

// ---- packed fp32x2 helpers (sm_100+) ----
__device__ __forceinline__ unsigned long long pack2(float a, float b) {
    unsigned long long v;
    asm("mov.b64 %0, {%1, %2};" : "=l"(v) : "f"(a), "f"(b));
    return v;
}
__device__ __forceinline__ void unpack2(unsigned long long v, float& a, float& b) {
    asm("mov.b64 {%0, %1}, %2;" : "=f"(a), "=f"(b) : "l"(v));
}
__device__ __forceinline__ void ffma2(unsigned long long& d,
                                      unsigned long long a, unsigned long long b) {
    asm("fma.rn.f32x2 %0, %1, %2, %0;" : "+l"(d) : "l"(a), "l"(b));
}

#define WP_STRIDE 65   // float2 stride for wpair (break STS/bank patterns)

// ---------------- kernel 1: u = (W1+W2)@x, v = W2@x  ->  [node][o] ----------
// grid (256, 4) -> 64 nodes/block, 256 threads, 3 blocks/SM (24 warps).
// Per thread: 4 nodes x 4 channels (acc = 32 regs).
// dynamic smem: wpair 64x65 float2 (33280B) + xs 64x64 float (16384B) = 49664B
__global__ __launch_bounds__(256, 3) void gemm_kernel(const float* __restrict__ x,
                                                      const float* __restrict__ W) {
    extern __shared__ __align__(16) float sblob[];
    float2* wpair = (float2*)sblob;                 // [c][o] stride WP_STRIDE
    float*  xs    = sblob + 64 * WP_STRIDE * 2;     // [c][nn] 64x64

    const int tid = threadIdx.x;
    const int b   = blockIdx.y;
    const int n0  = blockIdx.x * 64;

    // zero the stat accumulators (must happen every replay)
    if (blockIdx.x == 0 && blockIdx.y == 0 && tid < NCH) {
        g_s1[tid] = 0.f; g_s2[tid] = 0.f;
    }

    for (int i = tid; i < 4096; i += 256) {
        int o = i >> 6, c = i & 63;                 // coalesced W reads over c
        float w1 = W[o * 128 + c];
        float w2 = W[o * 128 + 64 + c];
        wpair[c * WP_STRIDE + o] = make_float2(w1 + w2, w2);
    }
    for (int i = tid; i < 4096; i += 256) {
        int c = i >> 6, nn = i & 63;
        xs[i] = x[((b * 64 + c) << 14) + n0 + nn];
    }
    __syncthreads();

    const int ng = tid >> 4;   // 0..15 -> nodes ng*4 .. ng*4+3
    const int og = tid & 15;   // channels o = og + 16*j, j=0..3

    unsigned long long acc[4][4];   // acc[i][j] = (u, v) node i, chan og+16j
    #pragma unroll
    for (int i = 0; i < 4; i++)
        #pragma unroll
        for (int j = 0; j < 4; j++) acc[i][j] = 0ull;

    const unsigned long long* wp = (const unsigned long long*)wpair;

    #pragma unroll 2
    for (int c = 0; c < 64; c++) {
        float4 xv = *(const float4*)(xs + c * 64 + ng * 4);
        unsigned long long xi[4];
        xi[0] = pack2(xv.x, xv.x);
        xi[1] = pack2(xv.y, xv.y);
        xi[2] = pack2(xv.z, xv.z);
        xi[3] = pack2(xv.w, xv.w);
        #pragma unroll
        for (int j = 0; j < 4; j++) {
            unsigned long long w = wp[c * WP_STRIDE + og + 16 * j];  // (wsum, w2)
            #pragma unroll
            for (int i = 0; i < 4; i++) ffma2(acc[i][j], w, xi[i]);
        }
    }

    __syncthreads();           // done reading smem; reuse xs region as [nn][o]
    float* vst = xs;

    const int node_base = (b << 14) + n0;
    #pragma unroll
    for (int i = 0; i < 4; i++) {
        int nn   = ng * 4 + i;
        int base = (node_base + nn) * 64 + og;
        #pragma unroll
        for (int j = 0; j < 4; j++) {
            float uu, vv;
            unpack2(acc[i][j], uu, vv);
            g_u[base + 16 * j] = uu;            // 64B-chunk coalesced
            vst[nn * 64 + og + 16 * j] = vv;    // stage for half2 pack
        }
    }
    __syncthreads();

    // coalesced half2 writes of v: 2048 half2 per block
    for (int t = tid; t < 2048; t += 256) {
        int nn = t >> 5, cp = t & 31;
        float2 vv = ((const float2*)(vst + nn * 64))[cp];
        g_vh[(node_base + nn) * 32 + cp] = __floats2half2_rn(vv.x, vv.y);
    }
}

// ---------------- kernel 2: gather v(fp16), min/max over K, channel stats ---
// grid 1024, block 256 (8 warps). One warp per node, 8 nodes per warp.
__global__ __launch_bounds__(256) void gather_kernel(const int* __restrict__ ei) {
    const int warp = threadIdx.x >> 5;
    const int lane = threadIdx.x & 31;

    __shared__ float sh1[NCH], sh2[NCH];
    if (threadIdx.x < NCH) { sh1[threadIdx.x] = 0.f; sh2[threadIdx.x] = 0.f; }
    __syncthreads();

    float a1x = 0.f, a1y = 0.f, a2x = 0.f, a2y = 0.f;
    const int node0 = blockIdx.x * 64 + warp * 8;
    const int b     = node0 >> 14;            // constant for whole block
    const int vbase = (b << 14) * 32;

    const float2*  up = (const float2*)g_u;
    const __half2* vp = g_vh;

    for (int t = 0; t < 8; t++) {
        const int g = node0 + t;              // global node id = b*16384 + n
        const int kidx = ei[(g << 4) + (lane & 15)];

        float2 u = up[g * 32 + lane];
        float2 vmin = make_float2(3.0e38f, 3.0e38f);
        float2 vmax = make_float2(-3.0e38f, -3.0e38f);
        float2 s1 = make_float2(0.f, 0.f);
        float2 s2 = make_float2(0.f, 0.f);

        #pragma unroll
        for (int k = 0; k < 16; k++) {
            int m = __shfl_sync(0xffffffffu, kidx, k);
            float2 vv = __half22float2(vp[vbase + m * 32 + lane]);
            vmin.x = fminf(vmin.x, vv.x); vmin.y = fminf(vmin.y, vv.y);
            vmax.x = fmaxf(vmax.x, vv.x); vmax.y = fmaxf(vmax.y, vv.y);
            s1.x += vv.x;          s1.y += vv.y;
            s2.x = fmaf(vv.x, vv.x, s2.x);
            s2.y = fmaf(vv.y, vv.y, s2.y);
        }

        g_hmax[g * 32 + lane] = __floats2half2_rn(u.x - vmin.x, u.y - vmin.y);
        g_hmin[g * 32 + lane] = __floats2half2_rn(u.x - vmax.x, u.y - vmax.y);

        a1x += 16.f * u.x - s1.x;
        a1y += 16.f * u.y - s1.y;
        a2x += 16.f * u.x * u.x - 2.f * u.x * s1.x + s2.x;
        a2y += 16.f * u.y * u.y - 2.f * u.y * s1.y + s2.y;
    }

    atomicAdd(&sh1[lane * 2],     a1x);
    atomicAdd(&sh1[lane * 2 + 1], a1y);
    atomicAdd(&sh2[lane * 2],     a2x);
    atomicAdd(&sh2[lane * 2 + 1], a2y);
    __syncthreads();
    if (threadIdx.x < NCH) {
        atomicAdd(&g_s1[threadIdx.x], sh1[threadIdx.x]);
        atomicAdd(&g_s2[threadIdx.x], sh2[threadIdx.x]);
    }
}

// ---------------- kernel 3: finalize BN, leaky-relu, max, transpose out -----
// grid (256, 4), block 256.
__global__ __launch_bounds__(256) void out_kernel(const float* __restrict__ gamma,
                                                  const float* __restrict__ beta,
                                                  float* __restrict__ out) {
    __shared__ float sc_s[NCH], sh_s[NCH];
    __shared__ float tile[64 * 65];
    const int tid = threadIdx.x;

    if (tid < NCH) {
        const float inv = 1.0f / 1048576.0f;   // B*N*K samples
        float m   = g_s1[tid] * inv;
        float var = fmaf(-m, m, g_s2[tid] * inv);
        float sc  = gamma[tid] * rsqrtf(var + 1e-5f);
        sc_s[tid] = sc;
        sh_s[tid] = fmaf(-m, sc, beta[tid]);
    }
    __syncthreads();

    const int b = blockIdx.y;
    const int n0 = blockIdx.x * 64;

    for (int i = tid; i < 2048; i += 256) {
        int nn = i >> 5, cp = i & 31;
        int g = (b << 14) + n0 + nn;
        float2 hM = __half22float2(g_hmax[g * 32 + cp]);
        float2 hm = __half22float2(g_hmin[g * 32 + cp]);
        int o0 = cp * 2, o1 = o0 + 1;
        // BN+leaky monotone in h -> max over K is max of f(hmax), f(hmin)
        float aM0 = fmaf(sc_s[o0], hM.x, sh_s[o0]); aM0 = (aM0 >= 0.f) ? aM0 : 0.2f * aM0;
        float am0 = fmaf(sc_s[o0], hm.x, sh_s[o0]); am0 = (am0 >= 0.f) ? am0 : 0.2f * am0;
        float aM1 = fmaf(sc_s[o1], hM.y, sh_s[o1]); aM1 = (aM1 >= 0.f) ? aM1 : 0.2f * aM1;
        float am1 = fmaf(sc_s[o1], hm.y, sh_s[o1]); am1 = (am1 >= 0.f) ? am1 : 0.2f * am1;
        tile[o0 * 65 + nn] = fmaxf(aM0, am0);
        tile[o1 * 65 + nn] = fmaxf(aM1, am1);
    }
    __syncthreads();

    for (int i = tid; i < 4096; i += 256) {
        int nn = i & 63, o = i >> 6;
        out[((b * 64 + o) << 14) + n0 + nn] = tile[o * 65 + nn];
    }
}

extern "C" void kernel_launch(void* const* d_in, const int* in_sizes, int n_in,
                              void* d_out, int out_size) {
    const float* x     = (const float*)d_in[0];   // (4,64,16384,1) f32
    const int*   ei    = (const int*)  d_in[1];   // (4,16384,16) i32
    const float* W     = (const float*)d_in[2];   // (64,128) f32
    const float* gamma = (const float*)d_in[3];   // (64,) f32
    const float* beta  = (const float*)d_in[4];   // (64,) f32
    float* out = (float*)d_out;                   // (4,64,16384,1) f32

    const int smem_bytes = (64 * WP_STRIDE * 2 + 64 * 64) * 4;   // 49664
    cudaFuncSetAttribute(gemm_kernel,
                         cudaFuncAttributeMaxDynamicSharedMemorySize, smem_bytes);

    gemm_kernel<<<dim3(256, 4), 256, smem_bytes>>>(x, W);
    gather_kernel<<<1024, 256>>>(ei);
    out_kernel<<<dim3(256, 4), 256>>>(gamma, beta, out);
}

// round 17
// speedup vs baseline: 1.4418x; 1.4418x over previous
#include <cuda_runtime.h>
#include <cuda_fp16.h>
#include <mma.h>
#include <cstdint>

using namespace nvcuda;

// Problem constants: B=4, C=CO=64, N=16384, K=16
#define NPTS   16384
#define NODES  (4 * NPTS)          // 65536
#define NCH    64

// Scratch (device globals; no allocation allowed)
__device__ __align__(16) float   g_u[NODES * NCH];      // u[node][o]  fp32
__device__ __align__(16) __half2 g_vh[NODES * 32];      // v[node][o]  fp16
__device__ __align__(16) __half2 g_hmax[NODES * 32];    // max_k h  fp16
__device__ __align__(16) __half2 g_hmin[NODES * 32];    // min_k h  fp16
__device__ float g_s1[NCH];                             // sum h   per channel
__device__ float g_s2[NCH];                             // sum h^2 per channel

#define XS2 72   // halfs per A m-row (pad: ldm multiple of 8, conflict-spread)
#define WB2 72   // halfs per B n-row

// ---------------- kernel 1: WMMA GEMM: u,v for 128 nodes per CTA ------------
// grid 512, block 256 (8 warps, 16 nodes/warp).
// D[128m x 128n] = A[128m x 64k] * B[128n x 64k]^T ; n<64 -> u, n>=64 -> v
// Fragment layouts are COMPILER-OWNED via nvcuda::wmma (no hand-rolled maps).
__global__ __launch_bounds__(256) void gemm_wmma_kernel(const float* __restrict__ x,
                                                        const float* __restrict__ W) {
    __shared__ __align__(16) __half xsA[128 * XS2];   // A: [m][k]  18432B
    __shared__ __align__(16) __half wb [128 * WB2];   // B: [n][k]  18432B
    __shared__ __align__(16) float  stg[8][256];      // per-warp v staging 8KB

    const int tid  = threadIdx.x;
    const int warp = tid >> 5;
    const int lane = tid & 31;

    // zero the stat accumulators (must happen every replay)
    if (blockIdx.x == 0 && tid < NCH) { g_s1[tid] = 0.f; g_s2[tid] = 0.f; }

    const int node0 = blockIdx.x * 128;
    const int b  = node0 >> 14;
    const int nb = node0 & 16383;

    // B tile: row n<64 = W1[n]+W2[n] (-> u), row n>=64 = W2[n-64] (-> v)
    for (int i = tid; i < 8192; i += 256) {
        int n = i >> 6, c = i & 63;
        float val = (n < 64) ? (W[n * 128 + c] + W[n * 128 + 64 + c])
                             : W[(n - 64) * 128 + 64 + c];
        wb[n * WB2 + c] = __float2half_rn(val);
    }
    // A tile: xsA[m][c] = x[c][node0+m]; coalesced gmem reads over m
    for (int i = tid; i < 8192; i += 256) {
        int c = i >> 7, m = i & 127;
        xsA[m * XS2 + c] = __float2half_rn(x[((b * 64 + c) << 14) + nb + m]);
    }
    __syncthreads();

    const int m0 = warp * 16;

    // A fragments: 4 k-steps, loaded once (xsA stays live; no smem reuse)
    wmma::fragment<wmma::matrix_a, 16, 16, 16, __half, wmma::row_major> af[4];
    #pragma unroll
    for (int ks = 0; ks < 4; ks++)
        wmma::load_matrix_sync(af[ks], xsA + m0 * XS2 + ks * 16, XS2);

    #pragma unroll
    for (int j = 0; j < 8; j++) {           // n-tiles of 16 channels
        wmma::fragment<wmma::accumulator, 16, 16, 16, float> d;
        wmma::fill_fragment(d, 0.0f);
        #pragma unroll
        for (int ks = 0; ks < 4; ks++) {
            // B[k][n] := wb[j*16+n][k]  -> col_major at wb + j*16*WB2, ldm WB2
            wmma::fragment<wmma::matrix_b, 16, 16, 16, __half, wmma::col_major> bf;
            wmma::load_matrix_sync(bf, wb + j * 16 * WB2 + ks * 16, WB2);
            wmma::mma_sync(d, af[ks], bf, d);
        }
        if (j < 4) {
            // u: direct fp32 row-major store, ldm 64
            wmma::store_matrix_sync(g_u + (node0 + m0) * 64 + j * 16, d, 64,
                                    wmma::mem_row_major);
        } else {
            // v: stage fp32 -> convert half2 -> g_vh
            wmma::store_matrix_sync(stg[warp], d, 16, wmma::mem_row_major);
            __syncwarp();
            #pragma unroll
            for (int idx = lane; idx < 128; idx += 32) {
                int r = idx >> 3, c2 = idx & 7;
                float2 vv = *(const float2*)&stg[warp][r * 16 + 2 * c2];
                g_vh[(node0 + m0 + r) * 32 + (j - 4) * 8 + c2] =
                    __floats2half2_rn(vv.x, vv.y);
            }
            __syncwarp();   // protect stg before next j overwrites it
        }
    }
}

// ---------------- kernel 2: gather v(fp16), min/max over K, channel stats ---
// grid 1024, block 256 (8 warps). One warp per node, 8 nodes per warp.
__global__ __launch_bounds__(256) void gather_kernel(const int* __restrict__ ei) {
    const int warp = threadIdx.x >> 5;
    const int lane = threadIdx.x & 31;

    __shared__ float sh1[NCH], sh2[NCH];
    if (threadIdx.x < NCH) { sh1[threadIdx.x] = 0.f; sh2[threadIdx.x] = 0.f; }
    __syncthreads();

    float a1x = 0.f, a1y = 0.f, a2x = 0.f, a2y = 0.f;
    const int node0 = blockIdx.x * 64 + warp * 8;
    const int b     = node0 >> 14;
    const int vbase = (b << 14) * 32;

    const float2*  up = (const float2*)g_u;
    const __half2* vp = g_vh;

    for (int t = 0; t < 8; t++) {
        const int g = node0 + t;
        const int kidx = ei[(g << 4) + (lane & 15)];

        float2 u = up[g * 32 + lane];
        float2 vmin = make_float2(3.0e38f, 3.0e38f);
        float2 vmax = make_float2(-3.0e38f, -3.0e38f);
        float2 s1 = make_float2(0.f, 0.f);
        float2 s2 = make_float2(0.f, 0.f);

        #pragma unroll
        for (int k = 0; k < 16; k++) {
            int m = __shfl_sync(0xffffffffu, kidx, k);
            float2 vv = __half22float2(vp[vbase + m * 32 + lane]);
            vmin.x = fminf(vmin.x, vv.x); vmin.y = fminf(vmin.y, vv.y);
            vmax.x = fmaxf(vmax.x, vv.x); vmax.y = fmaxf(vmax.y, vv.y);
            s1.x += vv.x;          s1.y += vv.y;
            s2.x = fmaf(vv.x, vv.x, s2.x);
            s2.y = fmaf(vv.y, vv.y, s2.y);
        }

        g_hmax[g * 32 + lane] = __floats2half2_rn(u.x - vmin.x, u.y - vmin.y);
        g_hmin[g * 32 + lane] = __floats2half2_rn(u.x - vmax.x, u.y - vmax.y);

        a1x += 16.f * u.x - s1.x;
        a1y += 16.f * u.y - s1.y;
        a2x += 16.f * u.x * u.x - 2.f * u.x * s1.x + s2.x;
        a2y += 16.f * u.y * u.y - 2.f * u.y * s1.y + s2.y;
    }

    atomicAdd(&sh1[lane * 2],     a1x);
    atomicAdd(&sh1[lane * 2 + 1], a1y);
    atomicAdd(&sh2[lane * 2],     a2x);
    atomicAdd(&sh2[lane * 2 + 1], a2y);
    __syncthreads();
    if (threadIdx.x < NCH) {
        atomicAdd(&g_s1[threadIdx.x], sh1[threadIdx.x]);
        atomicAdd(&g_s2[threadIdx.x], sh2[threadIdx.x]);
    }
}

// ---------------- kernel 3: finalize BN, leaky-relu, max, transpose out -----
// grid (256, 4), block 256.
__global__ __launch_bounds__(256) void out_kernel(const float* __restrict__ gamma,
                                                  const float* __restrict__ beta,
                                                  float* __restrict__ out) {
    __shared__ float sc_s[NCH], sh_s[NCH];
    __shared__ float tile[64 * 65];
    const int tid = threadIdx.x;

    if (tid < NCH) {
        const float inv = 1.0f / 1048576.0f;   // B*N*K samples
        float m   = g_s1[tid] * inv;
        float var = fmaf(-m, m, g_s2[tid] * inv);
        float sc  = gamma[tid] * rsqrtf(var + 1e-5f);
        sc_s[tid] = sc;
        sh_s[tid] = fmaf(-m, sc, beta[tid]);
    }
    __syncthreads();

    const int b = blockIdx.y;
    const int n0 = blockIdx.x * 64;

    for (int i = tid; i < 2048; i += 256) {
        int nn = i >> 5, cp = i & 31;
        int g = (b << 14) + n0 + nn;
        float2 hM = __half22float2(g_hmax[g * 32 + cp]);
        float2 hm = __half22float2(g_hmin[g * 32 + cp]);
        int o0 = cp * 2, o1 = o0 + 1;
        // BN+leaky monotone in h -> max over K is max of f(hmax), f(hmin)
        float aM0 = fmaf(sc_s[o0], hM.x, sh_s[o0]); aM0 = (aM0 >= 0.f) ? aM0 : 0.2f * aM0;
        float am0 = fmaf(sc_s[o0], hm.x, sh_s[o0]); am0 = (am0 >= 0.f) ? am0 : 0.2f * am0;
        float aM1 = fmaf(sc_s[o1], hM.y, sh_s[o1]); aM1 = (aM1 >= 0.f) ? aM1 : 0.2f * aM1;
        float am1 = fmaf(sc_s[o1], hm.y, sh_s[o1]); am1 = (am1 >= 0.f) ? am1 : 0.2f * am1;
        tile[o0 * 65 + nn] = fmaxf(aM0, am0);
        tile[o1 * 65 + nn] = fmaxf(aM1, am1);
    }
    __syncthreads();

    for (int i = tid; i < 4096; i += 256) {
        int nn = i & 63, o = i >> 6;
        out[((b * 64 + o) << 14) + n0 + nn] = tile[o * 65 + nn];
    }
}

extern "C" void kernel_launch(void* const* d_in, const int* in_sizes, int n_in,
                              void* d_out, int out_size) {
    const float* x     = (const float*)d_in[0];   // (4,64,16384,1) f32
    const int*   ei    = (const int*)  d_in[1];   // (4,16384,16) i32
    const float* W     = (const float*)d_in[2];   // (64,128) f32
    const float* gamma = (const float*)d_in[3];   // (64,) f32
    const float* beta  = (const float*)d_in[4];   // (64,) f32
    float* out = (float*)d_out;                   // (4,64,16384,1) f32

    gemm_wmma_kernel<<<512, 256>>>(x, W);
    gather_kernel<<<1024, 256>>>(ei);
    out_kernel<<<dim3(256, 4), 256>>>(gamma, beta, out);
}